// round 8
// baseline (speedup 1.0000x reference)
#include <cuda_runtime.h>

#define B_    4
#define C_    32
#define H_    128
#define W_    256
#define HW_   (H_*W_)        // 32768
#define CHW_  (C_*HW_)       // 1048576
#define WW_   (W_*W_)        // 65536
#define BHWW_ (B_*H_*WW_)    // 33554432
#define XN_   (B_*CHW_)      // 4194304
#define NPIX_ (B_*H_*W_)     // 131072

typedef unsigned long long ull;

// q/k scratch: [side][pixel][channel], side 0 = from x_left, 1 = from x_right
__device__ float g_q[2][NPIX_ * C_];
__device__ float g_k[2][NPIX_ * C_];

// Band tiles (d=0 frame: delta = it-jt in [0,3]) and off-band tiles.
__constant__ unsigned char CTILE[26] = {
    0, 9, 18, 27, 36, 45, 54, 63,
    8, 17, 26, 35, 44, 53, 62,
    16, 25, 34, 43, 52, 61,
    24, 33, 42, 51, 60
};
__constant__ unsigned char CPTILE[38] = {
    1, 2, 3, 4, 5, 6, 7,
    10, 11, 12, 13, 14, 15,
    19, 20, 21, 22, 23,
    28, 29, 30, 31,
    32, 37, 38, 39,
    40, 41, 46, 47,
    48, 49, 50, 55,
    56, 57, 58, 59
};

// ---- packed f32x2 helpers (Blackwell sm_103a) ----
__device__ __forceinline__ ull pack2(float lo, float hi) {
    ull r;
    asm("mov.b64 %0, {%1, %2};" : "=l"(r) : "f"(lo), "f"(hi));
    return r;
}
__device__ __forceinline__ void fma2(ull &d, ull a, ull b) {
    asm("fma.rn.f32x2 %0, %1, %2, %0;" : "+l"(d) : "l"(a), "l"(b));
}
__device__ __forceinline__ ull add2(ull a, ull b) {
    ull r;
    asm("add.rn.f32x2 %0, %1, %2;" : "=l"(r) : "l"(a), "l"(b));
    return r;
}
__device__ __forceinline__ float sum2(ull a) {
    float lo, hi;
    asm("mov.b64 {%0, %1}, %2;" : "=f"(lo), "=f"(hi) : "l"(a));
    return lo + hi;
}

// ============================================================
// K1: projections + x*2 passthrough.  block = (bh, side)
// ============================================================
extern "C" __global__ void __launch_bounds__(256)
proj_kernel(const float* __restrict__ x_left, const float* __restrict__ x_right,
            const float* __restrict__ qw, const float* __restrict__ qb,
            const float* __restrict__ qg, const float* __restrict__ qbe,
            const float* __restrict__ qm, const float* __restrict__ qv,
            const float* __restrict__ kw, const float* __restrict__ kb,
            const float* __restrict__ kg, const float* __restrict__ kbe,
            const float* __restrict__ km, const float* __restrict__ kv,
            float* __restrict__ out)
{
    __shared__ float wq[1024], wk[1024], bq[32], bk[32];
    const int tid  = threadIdx.x;
    const int side = blockIdx.x & 1;
    const int bh   = blockIdx.x >> 1;

    for (int t = tid; t < 1024; t += 256) {
        const int o = t >> 5;
        wq[t] = qw[t] * (qg[o] * rsqrtf(qv[o] + 1e-5f));
        wk[t] = kw[t] * (kg[o] * rsqrtf(kv[o] + 1e-5f));
    }
    if (tid < 32) {
        const float sq = qg[tid] * rsqrtf(qv[tid] + 1e-5f);
        const float sk = kg[tid] * rsqrtf(kv[tid] + 1e-5f);
        bq[tid] = qb[tid] * sq + qbe[tid] - qm[tid] * sq;
        bk[tid] = kb[tid] * sk + kbe[tid] - km[tid] * sk;
    }
    __syncthreads();

    const long base = (long)(bh >> 7) * CHW_ + (long)(bh & 127) * W_ + tid;
    const float* xs = side ? x_right : x_left;

    float xv[32];
    #pragma unroll
    for (int c = 0; c < 32; c++) xv[c] = xs[base + (long)c * HW_];

    {
        float* ox = out + (side ? XN_ : 0) + base;
        #pragma unroll
        for (int c = 0; c < 32; c++) __stcs(ox + (long)c * HW_, 2.0f * xv[c]);
    }

    ull x2[16];
    #pragma unroll
    for (int c2 = 0; c2 < 16; c2++) x2[c2] = pack2(xv[2*c2], xv[2*c2+1]);

    const long pidx = ((long)bh * W_ + tid) * 32;
    float4* qdst = (float4*)(g_q[side] + pidx);
    float4* kdst = (float4*)(g_k[side] + pidx);

    #pragma unroll
    for (int og = 0; og < 8; og++) {
        float4 r;
        #pragma unroll
        for (int u = 0; u < 4; u++) {
            const int o = og * 4 + u;
            ull a0 = 0ull, a1 = 0ull;
            const ull* wr = (const ull*)(wq + o * 32);
            #pragma unroll
            for (int c2 = 0; c2 < 16; c2 += 2) {
                fma2(a0, wr[c2],   x2[c2]);
                fma2(a1, wr[c2+1], x2[c2+1]);
            }
            (&r.x)[u] = sum2(add2(a0, a1)) + bq[o];
        }
        qdst[og] = r;
    }
    #pragma unroll
    for (int og = 0; og < 8; og++) {
        float4 r;
        #pragma unroll
        for (int u = 0; u < 4; u++) {
            const int o = og * 4 + u;
            ull a0 = 0ull, a1 = 0ull;
            const ull* wr = (const ull*)(wk + o * 32);
            #pragma unroll
            for (int c2 = 0; c2 < 16; c2 += 2) {
                fma2(a0, wr[c2],   x2[c2]);
                fma2(a1, wr[c2+1], x2[c2+1]);
            }
            (&r.x)[u] = sum2(add2(a0, a1)) + bk[o];
        }
        kdst[og] = r;
    }
}

// ============================================================
// K2: off-band pure copy.  one warp = one 32x32 tile
// ============================================================
extern "C" __global__ void __launch_bounds__(256)
copy_kernel(const float* __restrict__ cost, float* __restrict__ out)
{
    const int warp = threadIdx.x >> 5, lane = threadIdx.x & 31;
    const int job = blockIdx.x * 8 + warp;          // < 38912
    const int dbh = job / 38;
    const int tt  = job - dbh * 38;
    const int d = dbh & 1, bh = dbh >> 1;
    const int code = CPTILE[tt];
    int it = code >> 3, jt = code & 7;
    if (d) { const int tmp = it; it = jt; jt = tmp; }

    const size_t off = (size_t)d * BHWW_ + (size_t)bh * WW_ + (size_t)(it * 32) * W_ + jt * 32;
    const float* cpt = cost + off;
    float*       opt = out + 2 * (size_t)XN_ + off;
    const int r0 = lane >> 3, c4 = (lane & 7) << 2;

    float4 v[8];
    #pragma unroll
    for (int t = 0; t < 8; t++)
        v[t] = __ldcs((const float4*)(cpt + (size_t)((t << 2) + r0) * W_ + c4));
    #pragma unroll
    for (int t = 0; t < 8; t++)
        __stcs((float4*)(opt + (size_t)((t << 2) + r0) * W_ + c4), v[t]);
}

// ============================================================
// K3: band tiles.  one warp = one 32x32 tile; lane = row i.
// q row in regs (coalesced), k rows via uniform L2-hot loads,
// no cross-lane reduction; scores staged stride-33 in smem.
// ============================================================
extern "C" __global__ void __launch_bounds__(256, 3)
band_kernel(const float* __restrict__ cost, float* __restrict__ out)
{
    __shared__ float sw[8 * 1056];
    const int tid = threadIdx.x, warp = tid >> 5, lane = tid & 31;
    const int job = blockIdx.x * 8 + warp;          // < 26624
    const int dbh = job / 26;
    const int tt  = job - dbh * 26;
    const int d = dbh & 1, bh = dbh >> 1;
    const int code = CTILE[tt];
    int it = code >> 3, jt = code & 7;
    if (d) { const int tmp = it; it = jt; jt = tmp; }

    const float* qsrc = (d ? g_q[1] : g_q[0]) + (long)bh * W_ * 32;
    const float* ksrc = (d ? g_k[0] : g_k[1]) + (long)bh * W_ * 32;

    // load this lane's q row (4KB coalesced per warp)
    const int ii = it * 32 + lane;
    ull q2[16];
    {
        const float4* qp = (const float4*)(qsrc + (long)ii * 32);
        #pragma unroll
        for (int t = 0; t < 8; t++) {
            const float4 v = __ldg(qp + t);
            q2[2*t]   = pack2(v.x, v.y);
            q2[2*t+1] = pack2(v.z, v.w);
        }
    }

    float* swp = sw + warp * 1056;
    const float4* kp0 = (const float4*)(ksrc + (long)(jt * 32) * 32);
    const float inv_c = 1.0f / 32.0f;

    #pragma unroll 4
    for (int j = 0; j < 32; j++) {
        const float4* kp = kp0 + j * 8;
        float4 kv[8];
        #pragma unroll
        for (int t = 0; t < 8; t++) kv[t] = __ldg(kp + t);

        ull a0 = 0ull, a1 = 0ull, a2 = 0ull, a3 = 0ull;
        #pragma unroll
        for (int t = 0; t < 4; t++) {
            fma2(a0, q2[4*t],   pack2(kv[2*t].x,   kv[2*t].y));
            fma2(a1, q2[4*t+1], pack2(kv[2*t].z,   kv[2*t].w));
            fma2(a2, q2[4*t+2], pack2(kv[2*t+1].x, kv[2*t+1].y));
            fma2(a3, q2[4*t+3], pack2(kv[2*t+1].z, kv[2*t+1].w));
        }
        const float s = sum2(add2(add2(a0, a1), add2(a2, a3))) * inv_c;
        const int jj = jt * 32 + j;
        const int diff = d ? (jj - ii) : (ii - jj);
        swp[lane * 33 + j] = ((unsigned)diff < 85u) ? s : 0.0f;
    }
    __syncwarp();

    // cost add + store (float4, conflict-free stride-33 scalar LDS)
    const size_t off = (size_t)d * BHWW_ + (size_t)bh * WW_ + (size_t)(it * 32) * W_ + jt * 32;
    const float* cpt = cost + off;
    float*       opt = out + 2 * (size_t)XN_ + off;
    const int r0 = lane >> 3, c4 = (lane & 7) << 2;

    #pragma unroll
    for (int t = 0; t < 8; t++) {
        const int row = (t << 2) + r0;
        const float4 c = __ldcs((const float4*)(cpt + (size_t)row * W_ + c4));
        const float* sp = swp + row * 33 + c4;
        float4 o;
        o.x = c.x + sp[0];
        o.y = c.y + sp[1];
        o.z = c.z + sp[2];
        o.w = c.w + sp[3];
        __stcs((float4*)(opt + (size_t)row * W_ + c4), o);
    }
}

extern "C" void kernel_launch(void* const* d_in, const int* in_sizes, int n_in,
                              void* d_out, int out_size)
{
    (void)in_sizes; (void)n_in; (void)out_size;
    const float* xl = (const float*)d_in[0];
    const float* xr = (const float*)d_in[1];
    const float* cost = (const float*)d_in[2];
    float* out = (float*)d_out;

    proj_kernel<<<2 * B_ * H_, 256>>>(
        xl, xr,
        (const float*)d_in[3],  (const float*)d_in[4],  (const float*)d_in[5],
        (const float*)d_in[6],  (const float*)d_in[7],  (const float*)d_in[8],
        (const float*)d_in[9],  (const float*)d_in[10], (const float*)d_in[11],
        (const float*)d_in[12], (const float*)d_in[13], (const float*)d_in[14],
        out);
    copy_kernel<<<4864, 256>>>(cost, out);
    band_kernel<<<3328, 256>>>(cost, out);
}

// round 9
// speedup vs baseline: 1.9777x; 1.9777x over previous
#include <cuda_runtime.h>

#define B_    4
#define C_    32
#define H_    128
#define W_    256
#define CR_   85
#define HW_   (H_*W_)        // 32768
#define CHW_  (C_*HW_)       // 1048576
#define WW_   (W_*W_)        // 65536
#define BHWW_ (B_*H_*WW_)    // 33554432
#define XN_   (B_*CHW_)      // 4194304
#define STR_  34             // padded row stride for smem q/k

typedef unsigned long long ull;

// Per-warp interleaved schedule: SCHED[w*8+n] = tile_code (it*8+jt, d=0 frame)
// | 0x80 if compute tile. Alternating copy/compute per warp.
__constant__ unsigned char SCHED[64] = {
    //  n=0     n=1     n=2     n=3     n=4     n=5     n=6     n=7
       1,   128+0,     2,   128+9,     3,  128+18,     4,  128+27,   // w0
    128+36,     5,  128+45,     6,  128+54,     7,  128+63,    10,   // w1
      11,   128+8,    12,  128+17,    13,  128+26,    14,    15,     // w2
    128+35,    19,  128+44,    20,  128+53,    21,    22,    23,     // w3
      28,  128+62,    29,  128+16,    30,  128+25,    31,    32,     // w4
    128+34,    37,  128+43,    38,  128+52,    39,    40,    41,     // w5
      46,  128+61,    47,  128+24,    48,  128+33,    49,    50,     // w6
    128+42,    55,  128+51,    56,  128+60,    57,    58,    59      // w7
};

// ---- packed f32x2 helpers (Blackwell sm_103a) ----
__device__ __forceinline__ ull pack2(float lo, float hi) {
    ull r;
    asm("mov.b64 %0, {%1, %2};" : "=l"(r) : "f"(lo), "f"(hi));
    return r;
}
__device__ __forceinline__ void fma2(ull &d, ull a, ull b) {
    asm("fma.rn.f32x2 %0, %1, %2, %0;" : "+l"(d) : "l"(a), "l"(b));
}
__device__ __forceinline__ ull add2(ull a, ull b) {
    ull r;
    asm("add.rn.f32x2 %0, %1, %2;" : "=l"(r) : "l"(a), "l"(b));
    return r;
}
__device__ __forceinline__ float sum2(ull a) {
    float lo, hi;
    asm("mov.b64 {%0, %1}, %2;" : "=f"(lo), "=f"(hi) : "l"(a));
    return lo + hi;
}
__device__ __forceinline__ unsigned smem_u32(const void* p) {
    unsigned a;
    asm("{ .reg .u64 t; cvta.to.shared.u64 t, %1; cvt.u32.u64 %0, t; }" : "=r"(a) : "l"(p));
    return a;
}
__device__ __forceinline__ void cpasync16(unsigned s, const void* g) {
    asm volatile("cp.async.cg.shared.global [%0], [%1], 16;" :: "r"(s), "l"(g));
}
#define CP_COMMIT() asm volatile("cp.async.commit_group;")
#define CP_WAIT0()  asm volatile("cp.async.wait_group 0;")

extern "C" __global__ void __launch_bounds__(256, 2)
pab_kernel(const float* __restrict__ x_left, const float* __restrict__ x_right,
           const float* __restrict__ cost,
           const float* __restrict__ qw, const float* __restrict__ qb,
           const float* __restrict__ qg, const float* __restrict__ qbe,
           const float* __restrict__ qm, const float* __restrict__ qv,
           const float* __restrict__ kw, const float* __restrict__ kb,
           const float* __restrict__ kg, const float* __restrict__ kbe,
           const float* __restrict__ km, const float* __restrict__ kv,
           float* __restrict__ out)
{
    extern __shared__ float sm[];
    float* qA  = sm;                     // [256][34]
    float* kA  = sm + 256 * STR_;        // [256][34]
    float* wqs = sm + 2 * 256 * STR_;    // [32][32] (reused as score staging)
    float* wks = wqs + 1024;             // [32][32] (reused as score staging)
    float* bqs = wks + 1024;             // [32]
    float* bks = bqs + 32;               // [32]
    float* cbuf = bks + 32;              // [8][1024] cp.async copy staging
    float* scoreB = wqs;                 // 8 warps x 256 floats

    const int tid  = threadIdx.x;
    const int warp = tid >> 5;
    const int lane = tid & 31;
    const int bx   = blockIdx.x;
    const int d    = bx & 1;
    const int bh   = bx >> 1;
    const int b    = bh >> 7;
    const int h    = bh & 127;

    const int r0 = lane >> 3;            // 0..3
    const int c4 = (lane & 7) << 2;      // 0,4,...,28

    const float* cbase = cost + (size_t)d * BHWW_ + (size_t)(b * H_ + h) * WW_;
    float*       obase = out  + (d ? (2*XN_ + BHWW_) : (2*XN_)) + (size_t)(b * H_ + h) * WW_;
    const unsigned mybuf = smem_u32(cbuf + warp * 1024);

    // issue cp.async for copy tile at slot m (lane pattern matches drain)
    auto issue_copy = [&](int m) {
        const int code = SCHED[(warp << 3) + m] & 63;
        int it = code >> 3, jt = code & 7;
        if (d) { const int tmp = it; it = jt; jt = tmp; }
        const float* cpt = cbase + (size_t)(it * 32) * W_ + jt * 32;
        #pragma unroll
        for (int t = 0; t < 8; t++) {
            const int row = (t << 2) + r0;
            cpasync16(mybuf + (unsigned)(row * 128 + c4 * 4),
                      cpt + (size_t)row * W_ + c4);
        }
        CP_COMMIT();
    };

    // ---- prime the pipeline: first copy tile streams under projection fma ----
    {
        int m = 0;
        while (m < 8 && (SCHED[(warp << 3) + m] & 128)) m++;
        if (m < 8) issue_copy(m);
    }

    // ---- fold BatchNorm into conv weights/bias ----
    for (int t = tid; t < 1024; t += 256) {
        const int o = t >> 5;
        wqs[t] = qw[t] * (qg[o] * rsqrtf(qv[o] + 1e-5f));
        wks[t] = kw[t] * (kg[o] * rsqrtf(kv[o] + 1e-5f));
    }
    if (tid < 32) {
        const float sq = qg[tid] * rsqrtf(qv[tid] + 1e-5f);
        const float sk = kg[tid] * rsqrtf(kv[tid] + 1e-5f);
        bqs[tid] = qb[tid] * sq + qbe[tid] - qm[tid] * sq;
        bks[tid] = kb[tid] * sk + kbe[tid] - km[tid] * sk;
    }
    __syncthreads();

    // ---- projections ----
    {
        const int i = tid;
        const long base = (long)b * CHW_ + (long)h * W_ + i;
        const float* xq = (d ? x_right : x_left) + base;
        const float* xk = (d ? x_left  : x_right) + base;

        {
            float xv[32];
            #pragma unroll
            for (int c = 0; c < 32; c++) xv[c] = xq[(long)c * HW_];
            float* ox = out + (d ? XN_ : 0) + base;
            #pragma unroll
            for (int c = 0; c < 32; c++) ox[(long)c * HW_] = 2.0f * xv[c];
            ull x2[16];
            #pragma unroll
            for (int c2 = 0; c2 < 16; c2++) x2[c2] = pack2(xv[2*c2], xv[2*c2+1]);
            #pragma unroll
            for (int o = 0; o < 32; o++) {
                ull a0 = 0ull, a1 = 0ull;
                const ull* wr = (const ull*)(wqs + o * 32);
                #pragma unroll
                for (int c2 = 0; c2 < 16; c2 += 2) {
                    fma2(a0, wr[c2],   x2[c2]);
                    fma2(a1, wr[c2+1], x2[c2+1]);
                }
                qA[i * STR_ + o] = sum2(add2(a0, a1)) + bqs[o];
            }
        }
        {
            float xv[32];
            #pragma unroll
            for (int c = 0; c < 32; c++) xv[c] = xk[(long)c * HW_];
            ull x2[16];
            #pragma unroll
            for (int c2 = 0; c2 < 16; c2++) x2[c2] = pack2(xv[2*c2], xv[2*c2+1]);
            #pragma unroll
            for (int o = 0; o < 32; o++) {
                ull a0 = 0ull, a1 = 0ull;
                const ull* wr = (const ull*)(wks + o * 32);
                #pragma unroll
                for (int c2 = 0; c2 < 16; c2 += 2) {
                    fma2(a0, wr[c2],   x2[c2]);
                    fma2(a1, wr[c2+1], x2[c2+1]);
                }
                kA[i * STR_ + o] = sum2(add2(a0, a1)) + bks[o];
            }
        }
    }
    __syncthreads();

    // ---- banded attention + pipelined cost stream ----
    const float inv_c = 1.0f / 32.0f;
    float* sw = scoreB + warp * 256;

    #pragma unroll 1
    for (int n = 0; n < 8; n++) {
        const int e = SCHED[(warp << 3) + n];
        const int code = e & 63;
        int it = code >> 3, jt = code & 7;
        if (d) { const int tmp = it; it = jt; jt = tmp; }
        float* opt = obase + (size_t)(it * 32) * W_ + jt * 32;

        if (e & 128) {
            // ---- compute tile ----
            const float* cpt = cbase + (size_t)(it * 32) * W_ + jt * 32;
            const int jj = jt * 32 + lane;
            ull k2[16];
            const ull* krow = (const ull*)(kA + jj * STR_);
            #pragma unroll
            for (int c2 = 0; c2 < 16; c2++) k2[c2] = krow[c2];

            float4 cv0 = __ldcs((const float4*)(cpt + (size_t)r0 * W_ + c4));
            float4 cv1 = __ldcs((const float4*)(cpt + (size_t)(r0 + 4) * W_ + c4));

            #pragma unroll
            for (int cc = 0; cc < 4; cc++) {
                #pragma unroll
                for (int rr = 0; rr < 8; rr++) {
                    const int ii = it * 32 + (cc << 3) + rr;
                    const ull* qrow = (const ull*)(qA + ii * STR_);
                    ull a0 = 0ull, a1 = 0ull, a2 = 0ull, a3 = 0ull;
                    #pragma unroll
                    for (int c2 = 0; c2 < 16; c2 += 4) {
                        fma2(a0, qrow[c2],   k2[c2]);
                        fma2(a1, qrow[c2+1], k2[c2+1]);
                        fma2(a2, qrow[c2+2], k2[c2+2]);
                        fma2(a3, qrow[c2+3], k2[c2+3]);
                    }
                    const float s = sum2(add2(add2(a0, a1), add2(a2, a3))) * inv_c;
                    const int diff = d ? (jj - ii) : (ii - jj);
                    const float sv = ((unsigned)diff < (unsigned)CR_) ? s : 0.0f;
                    sw[(rr << 5) + ((((lane >> 2) ^ rr) & 7) << 2) + (lane & 3)] = sv;
                }
                __syncwarp();
                const float4 s0 = *(const float4*)(sw + (r0 << 5) + ((((lane & 7) ^ r0) & 7) << 2));
                const float4 s1 = *(const float4*)(sw + ((r0 + 4) << 5) + ((((lane & 7) ^ (r0 + 4)) & 7) << 2));
                __syncwarp();

                const int ra = (cc << 3) + r0;
                const int rb = ra + 4;
                float4 n0 = cv0, n1 = cv1;
                if (cc < 3) {
                    n0 = __ldcs((const float4*)(cpt + (size_t)(ra + 8) * W_ + c4));
                    n1 = __ldcs((const float4*)(cpt + (size_t)(rb + 8) * W_ + c4));
                }
                float4 o0, o1;
                o0.x = cv0.x + s0.x; o0.y = cv0.y + s0.y; o0.z = cv0.z + s0.z; o0.w = cv0.w + s0.w;
                o1.x = cv1.x + s1.x; o1.y = cv1.y + s1.y; o1.z = cv1.z + s1.z; o1.w = cv1.w + s1.w;
                __stcs((float4*)(opt + (size_t)ra * W_ + c4), o0);
                __stcs((float4*)(opt + (size_t)rb * W_ + c4), o1);
                cv0 = n0; cv1 = n1;
            }
        } else {
            // ---- drain pipelined copy tile, then issue the next one ----
            CP_WAIT0();
            __syncwarp();
            const float* src = cbuf + warp * 1024;
            float4 v[8];
            #pragma unroll
            for (int t = 0; t < 8; t++)
                v[t] = *(const float4*)(src + ((t << 2) + r0) * 32 + c4);
            __syncwarp();
            int m = n + 1;
            while (m < 8 && (SCHED[(warp << 3) + m] & 128)) m++;
            if (m < 8) issue_copy(m);
            #pragma unroll
            for (int t = 0; t < 8; t++)
                __stcs((float4*)(opt + (size_t)((t << 2) + r0) * W_ + c4), v[t]);
        }
    }
}

extern "C" void kernel_launch(void* const* d_in, const int* in_sizes, int n_in,
                              void* d_out, int out_size)
{
    (void)in_sizes; (void)n_in; (void)out_size;
    // qA/kA 69632 + weights/bias 8448 + copy staging 32768 = 110848 bytes
    const int smem_bytes = (2 * 256 * STR_ + 2 * 1024 + 64 + 8 * 1024) * sizeof(float);
    cudaFuncSetAttribute(pab_kernel, cudaFuncAttributeMaxDynamicSharedMemorySize, smem_bytes);
    pab_kernel<<<2 * B_ * H_, 256, smem_bytes>>>(
        (const float*)d_in[0],  (const float*)d_in[1],  (const float*)d_in[2],
        (const float*)d_in[3],  (const float*)d_in[4],  (const float*)d_in[5],
        (const float*)d_in[6],  (const float*)d_in[7],  (const float*)d_in[8],
        (const float*)d_in[9],  (const float*)d_in[10], (const float*)d_in[11],
        (const float*)d_in[12], (const float*)d_in[13], (const float*)d_in[14],
        (float*)d_out);
}

// round 10
// speedup vs baseline: 2.0006x; 1.0116x over previous
#include <cuda_runtime.h>

#define B_    4
#define C_    32
#define H_    128
#define W_    256
#define CR_   85
#define HW_   (H_*W_)        // 32768
#define CHW_  (C_*HW_)       // 1048576
#define WW_   (W_*W_)        // 65536
#define BHWW_ (B_*H_*WW_)    // 33554432
#define XN_   (B_*CHW_)      // 4194304
#define STR_  34             // padded row stride for smem q/k

typedef unsigned long long ull;

// Schedule entries: type<<12 | codeA<<6 | codeB   (codes it*8+jt, d=0 frame)
// type: 0=copy(codeA), 1=single compute, 2=pair compute (same q-block after
// direction swap), 3=nop.
#define CE(x)   ((unsigned short)((0u<<12)|((x)<<6)))
#define SE(x)   ((unsigned short)((1u<<12)|((x)<<6)))
#define PE(a,b) ((unsigned short)((2u<<12)|((a)<<6)|(b)))
#define NE      ((unsigned short)0x3000)

// d=0: pairs share it (row-block) directly.
__constant__ unsigned short SCHED0[64] = {
    CE(1),  PE(9,8),   CE(2),  SE(0),      CE(3),  CE(4),  NE,     NE,
    CE(5),  PE(18,17), CE(6),  SE(16),     CE(7),  CE(10), NE,     NE,
    CE(11), PE(27,26), CE(12), PE(25,24),  CE(13), CE(14), NE,     NE,
    CE(15), PE(36,35), CE(19), PE(34,33),  CE(20), CE(21), NE,     NE,
    CE(22), PE(45,44), CE(23), PE(43,42),  CE(28), CE(29), NE,     NE,
    CE(30), PE(54,53), CE(31), PE(52,51),  CE(32), CE(37), NE,     NE,
    CE(38), PE(63,62), CE(39), CE(40),     CE(41), CE(46), CE(47), CE(48),
    CE(49), PE(61,60), CE(50), CE(55),     CE(56), CE(57), CE(58), CE(59)
};
// d=1: pairs share jt in d0 frame; after the in-kernel it<->jt swap they
// share the actual row-block.
__constant__ unsigned short SCHED1[64] = {
    CE(1),  PE(45,53), CE(2),  SE(63),     CE(3),  CE(4),  NE,     NE,
    CE(5),  PE(0,8),   CE(6),  SE(61),     CE(7),  CE(10), NE,     NE,
    CE(11), PE(16,24), CE(12), PE(9,17),   CE(13), CE(14), NE,     NE,
    CE(15), PE(25,33), CE(19), PE(18,26),  CE(20), CE(21), NE,     NE,
    CE(22), PE(34,42), CE(23), PE(27,35),  CE(28), CE(29), NE,     NE,
    CE(30), PE(43,51), CE(31), PE(36,44),  CE(32), CE(37), NE,     NE,
    CE(38), PE(52,60), CE(39), CE(40),     CE(41), CE(46), CE(47), CE(48),
    CE(49), PE(54,62), CE(50), CE(55),     CE(56), CE(57), CE(58), CE(59)
};

// ---- packed f32x2 helpers (Blackwell sm_103a) ----
__device__ __forceinline__ ull pack2(float lo, float hi) {
    ull r;
    asm("mov.b64 %0, {%1, %2};" : "=l"(r) : "f"(lo), "f"(hi));
    return r;
}
__device__ __forceinline__ void fma2(ull &d, ull a, ull b) {
    asm("fma.rn.f32x2 %0, %1, %2, %0;" : "+l"(d) : "l"(a), "l"(b));
}
__device__ __forceinline__ ull add2(ull a, ull b) {
    ull r;
    asm("add.rn.f32x2 %0, %1, %2;" : "=l"(r) : "l"(a), "l"(b));
    return r;
}
__device__ __forceinline__ float sum2(ull a) {
    float lo, hi;
    asm("mov.b64 {%0, %1}, %2;" : "=f"(lo), "=f"(hi) : "l"(a));
    return lo + hi;
}
__device__ __forceinline__ unsigned smem_u32(const void* p) {
    unsigned a;
    asm("{ .reg .u64 t; cvta.to.shared.u64 t, %1; cvt.u32.u64 %0, t; }" : "=r"(a) : "l"(p));
    return a;
}
__device__ __forceinline__ void cpasync16(unsigned s, const void* g) {
    asm volatile("cp.async.cg.shared.global [%0], [%1], 16;" :: "r"(s), "l"(g));
}
#define CP_COMMIT() asm volatile("cp.async.commit_group;")
#define CP_WAIT0()  asm volatile("cp.async.wait_group 0;")

__device__ __forceinline__ int swp_code(int c, int d) {
    return d ? (((c & 7) << 3) | (c >> 3)) : c;
}

extern "C" __global__ void __launch_bounds__(256, 2)
pab_kernel(const float* __restrict__ x_left, const float* __restrict__ x_right,
           const float* __restrict__ cost,
           const float* __restrict__ qw, const float* __restrict__ qb,
           const float* __restrict__ qg, const float* __restrict__ qbe,
           const float* __restrict__ qm, const float* __restrict__ qv,
           const float* __restrict__ kw, const float* __restrict__ kb,
           const float* __restrict__ kg, const float* __restrict__ kbe,
           const float* __restrict__ km, const float* __restrict__ kv,
           float* __restrict__ out)
{
    extern __shared__ float sm[];
    float* qA  = sm;                     // [256][34]
    float* kA  = sm + 8704;              // [256][34]
    float* wqs = sm + 17408;             // [1024] weights -> swA staging
    float* wks = wqs + 1024;             // [1024] weights -> swB staging
    float* bqs = wks + 1024;             // [32]
    float* bks = bqs + 32;               // [32]
    float* cbuf = bks + 32;              // [8][1024] cp.async copy staging

    const int tid  = threadIdx.x;
    const int warp = tid >> 5;
    const int lane = tid & 31;
    const int bx   = blockIdx.x;
    const int d    = bx & 1;
    const int bh   = bx >> 1;
    const int b    = bh >> 7;
    const int h    = bh & 127;

    const int r0 = lane >> 3;            // 0..3
    const int c4 = (lane & 7) << 2;      // 0,4,...,28

    const float* cbase = cost + (size_t)d * BHWW_ + (size_t)(b * H_ + h) * WW_;
    float*       obase = out  + (d ? (2*XN_ + BHWW_) : (2*XN_)) + (size_t)(b * H_ + h) * WW_;
    const unsigned mybuf = smem_u32(cbuf + warp * 1024);
    const unsigned short* sched = d ? SCHED1 : SCHED0;

    auto issue_copy = [&](int m) {
        const int code = swp_code((sched[(warp << 3) + m] >> 6) & 63, d);
        const int it = code >> 3, jt = code & 7;
        const float* cpt = cbase + (size_t)(it * 32) * W_ + jt * 32;
        #pragma unroll
        for (int t = 0; t < 8; t++) {
            const int row = (t << 2) + r0;
            cpasync16(mybuf + (unsigned)(row * 128 + c4 * 4),
                      cpt + (size_t)row * W_ + c4);
        }
        CP_COMMIT();
    };

    // prime pipeline: slot 0 is a copy for every warp
    issue_copy(0);

    // ---- fold BatchNorm into conv weights/bias ----
    for (int t = tid; t < 1024; t += 256) {
        const int o = t >> 5;
        wqs[t] = qw[t] * (qg[o] * rsqrtf(qv[o] + 1e-5f));
        wks[t] = kw[t] * (kg[o] * rsqrtf(kv[o] + 1e-5f));
    }
    if (tid < 32) {
        const float sq = qg[tid] * rsqrtf(qv[tid] + 1e-5f);
        const float sk = kg[tid] * rsqrtf(kv[tid] + 1e-5f);
        bqs[tid] = qb[tid] * sq + qbe[tid] - qm[tid] * sq;
        bks[tid] = kb[tid] * sk + kbe[tid] - km[tid] * sk;
    }
    __syncthreads();

    // ---- projections + x*2 ----
    {
        const int i = tid;
        const long base = (long)b * CHW_ + (long)h * W_ + i;
        const float* xq = (d ? x_right : x_left) + base;
        const float* xk = (d ? x_left  : x_right) + base;

        {
            float xv[32];
            #pragma unroll
            for (int c = 0; c < 32; c++) xv[c] = xq[(long)c * HW_];
            float* ox = out + (d ? XN_ : 0) + base;
            #pragma unroll
            for (int c = 0; c < 32; c++) ox[(long)c * HW_] = 2.0f * xv[c];
            ull x2[16];
            #pragma unroll
            for (int c2 = 0; c2 < 16; c2++) x2[c2] = pack2(xv[2*c2], xv[2*c2+1]);
            #pragma unroll
            for (int o = 0; o < 32; o++) {
                ull a0 = 0ull, a1 = 0ull;
                const ull* wr = (const ull*)(wqs + o * 32);
                #pragma unroll
                for (int c2 = 0; c2 < 16; c2 += 2) {
                    fma2(a0, wr[c2],   x2[c2]);
                    fma2(a1, wr[c2+1], x2[c2+1]);
                }
                qA[i * STR_ + o] = sum2(add2(a0, a1)) + bqs[o];
            }
        }
        {
            float xv[32];
            #pragma unroll
            for (int c = 0; c < 32; c++) xv[c] = xk[(long)c * HW_];
            ull x2[16];
            #pragma unroll
            for (int c2 = 0; c2 < 16; c2++) x2[c2] = pack2(xv[2*c2], xv[2*c2+1]);
            #pragma unroll
            for (int o = 0; o < 32; o++) {
                ull a0 = 0ull, a1 = 0ull;
                const ull* wr = (const ull*)(wks + o * 32);
                #pragma unroll
                for (int c2 = 0; c2 < 16; c2 += 2) {
                    fma2(a0, wr[c2],   x2[c2]);
                    fma2(a1, wr[c2+1], x2[c2+1]);
                }
                kA[i * STR_ + o] = sum2(add2(a0, a1)) + bks[o];
            }
        }
    }
    __syncthreads();   // also retires weight smem; wqs/wks become score staging

    const float inv_c = 1.0f / 32.0f;
    float* swA = wqs + (warp << 7);      // [4][32] per warp
    float* swB = wks + (warp << 7);

    #pragma unroll 1
    for (int n = 0; n < 8; n++) {
        const int entry = sched[(warp << 3) + n];
        const int type = entry >> 12;
        if (type == 3) continue;
        const int cA = swp_code((entry >> 6) & 63, d);

        if (type == 0) {
            // ---- drain pipelined copy tile, then issue the next one ----
            const int it = cA >> 3, jt = cA & 7;
            float* opt = obase + (size_t)(it * 32) * W_ + jt * 32;
            CP_WAIT0();
            __syncwarp();
            const float* src = cbuf + warp * 1024;
            float4 v[8];
            #pragma unroll
            for (int t = 0; t < 8; t++)
                v[t] = *(const float4*)(src + ((t << 2) + r0) * 32 + c4);
            __syncwarp();
            int m = n + 1;
            while (m < 8 && (sched[(warp << 3) + m] >> 12) != 0) m++;
            if (m < 8) issue_copy(m);
            #pragma unroll
            for (int t = 0; t < 8; t++)
                __stcs((float4*)(opt + (size_t)((t << 2) + r0) * W_ + c4), v[t]);
        } else if (type == 2) {
            // ---- pair of band tiles sharing the q block ----
            const int cB = swp_code(entry & 63, d);
            const int it = cA >> 3;
            const int jtA = cA & 7, jtB = cB & 7;
            const int jjA = (jtA << 5) + lane, jjB = (jtB << 5) + lane;

            ull ka[16], kb[16];
            {
                const ull* p = (const ull*)(kA + jjA * STR_);
                #pragma unroll
                for (int t = 0; t < 16; t++) ka[t] = p[t];
            }
            {
                const ull* p = (const ull*)(kA + jjB * STR_);
                #pragma unroll
                for (int t = 0; t < 16; t++) kb[t] = p[t];
            }

            const float* cptA = cbase + (size_t)(it * 32) * W_ + (jtA << 5);
            const float* cptB = cbase + (size_t)(it * 32) * W_ + (jtB << 5);
            float* optA = obase + (size_t)(it * 32) * W_ + (jtA << 5);
            float* optB = obase + (size_t)(it * 32) * W_ + (jtB << 5);

            #pragma unroll 1
            for (int cc = 0; cc < 8; cc++) {       // 4-row chunks
                const int row = (cc << 2) + r0;
                const float4 ca = __ldcs((const float4*)(cptA + (size_t)row * W_ + c4));
                const float4 cb = __ldcs((const float4*)(cptB + (size_t)row * W_ + c4));

                #pragma unroll
                for (int rr = 0; rr < 4; rr++) {
                    const int ii = (it << 5) + (cc << 2) + rr;
                    const ull* qrow = (const ull*)(qA + ii * STR_);
                    ull aA0 = 0ull, aA1 = 0ull, aB0 = 0ull, aB1 = 0ull;
                    #pragma unroll
                    for (int c2 = 0; c2 < 16; c2 += 2) {
                        const ull q0 = qrow[c2], q1 = qrow[c2+1];
                        fma2(aA0, q0, ka[c2]);   fma2(aB0, q0, kb[c2]);
                        fma2(aA1, q1, ka[c2+1]); fma2(aB1, q1, kb[c2+1]);
                    }
                    const float sA = sum2(add2(aA0, aA1)) * inv_c;
                    const float sB = sum2(add2(aB0, aB1)) * inv_c;
                    const int dA = d ? (jjA - ii) : (ii - jjA);
                    const int dB = d ? (jjB - ii) : (ii - jjB);
                    const int wi = (rr << 5) + ((((lane >> 2) ^ rr) & 7) << 2) + (lane & 3);
                    swA[wi] = ((unsigned)dA < (unsigned)CR_) ? sA : 0.0f;
                    swB[wi] = ((unsigned)dB < (unsigned)CR_) ? sB : 0.0f;
                }
                __syncwarp();
                const int ri = (r0 << 5) + ((((lane & 7) ^ r0) & 7) << 2);
                const float4 s0 = *(const float4*)(swA + ri);
                const float4 s1 = *(const float4*)(swB + ri);
                float4 oa, ob;
                oa.x = ca.x + s0.x; oa.y = ca.y + s0.y; oa.z = ca.z + s0.z; oa.w = ca.w + s0.w;
                ob.x = cb.x + s1.x; ob.y = cb.y + s1.y; ob.z = cb.z + s1.z; ob.w = cb.w + s1.w;
                __stcs((float4*)(optA + (size_t)row * W_ + c4), oa);
                __stcs((float4*)(optB + (size_t)row * W_ + c4), ob);
                __syncwarp();
            }
        } else {
            // ---- single band tile ----
            const int it = cA >> 3, jt = cA & 7;
            const int jj = (jt << 5) + lane;
            ull ka[16];
            {
                const ull* p = (const ull*)(kA + jj * STR_);
                #pragma unroll
                for (int t = 0; t < 16; t++) ka[t] = p[t];
            }
            const float* cpt = cbase + (size_t)(it * 32) * W_ + (jt << 5);
            float* opt = obase + (size_t)(it * 32) * W_ + (jt << 5);

            #pragma unroll 1
            for (int cc = 0; cc < 8; cc++) {
                const int row = (cc << 2) + r0;
                const float4 ca = __ldcs((const float4*)(cpt + (size_t)row * W_ + c4));
                #pragma unroll
                for (int rr = 0; rr < 4; rr++) {
                    const int ii = (it << 5) + (cc << 2) + rr;
                    const ull* qrow = (const ull*)(qA + ii * STR_);
                    ull a0 = 0ull, a1 = 0ull;
                    #pragma unroll
                    for (int c2 = 0; c2 < 16; c2 += 2) {
                        fma2(a0, qrow[c2],   ka[c2]);
                        fma2(a1, qrow[c2+1], ka[c2+1]);
                    }
                    const float s = sum2(add2(a0, a1)) * inv_c;
                    const int df = d ? (jj - ii) : (ii - jj);
                    swA[(rr << 5) + ((((lane >> 2) ^ rr) & 7) << 2) + (lane & 3)] =
                        ((unsigned)df < (unsigned)CR_) ? s : 0.0f;
                }
                __syncwarp();
                const float4 s0 = *(const float4*)(swA + (r0 << 5) + ((((lane & 7) ^ r0) & 7) << 2));
                float4 oa;
                oa.x = ca.x + s0.x; oa.y = ca.y + s0.y; oa.z = ca.z + s0.z; oa.w = ca.w + s0.w;
                __stcs((float4*)(opt + (size_t)row * W_ + c4), oa);
                __syncwarp();
            }
        }
    }
}

extern "C" void kernel_launch(void* const* d_in, const int* in_sizes, int n_in,
                              void* d_out, int out_size)
{
    (void)in_sizes; (void)n_in; (void)out_size;
    // qA/kA 69632 + staging/bias 8448 + copy staging 32768 = 110848 bytes
    const int smem_bytes = 110848;
    cudaFuncSetAttribute(pab_kernel, cudaFuncAttributeMaxDynamicSharedMemorySize, smem_bytes);
    pab_kernel<<<2 * B_ * H_, 256, smem_bytes>>>(
        (const float*)d_in[0],  (const float*)d_in[1],  (const float*)d_in[2],
        (const float*)d_in[3],  (const float*)d_in[4],  (const float*)d_in[5],
        (const float*)d_in[6],  (const float*)d_in[7],  (const float*)d_in[8],
        (const float*)d_in[9],  (const float*)d_in[10], (const float*)d_in[11],
        (const float*)d_in[12], (const float*)d_in[13], (const float*)d_in[14],
        (float*)d_out);
}